// round 9
// baseline (speedup 1.0000x reference)
#include <cuda_runtime.h>
#include <cuda_fp16.h>
#include <cstdint>

// Jacobian (3x12) of 3->64->64->64->64->12 SiLU MLP at N=1M points.
// mma.sync m16n8k16 fp16, fp32 accum. 2-term split ON WEIGHTS ONLY:
//   W = Wh + Wl (fp16 planes); product = x_f16*Wh + x_f16*Wl (residual ~2^-11).
// One warp owns a 16-point tile and ALL 4 vectors {h,t0,t1,t2}; D-accumulator
// fragments map register-locally onto next layer's A fragments.
// R9: A-fragments of t1,t2 live in per-LANE SMEM slots (same-thread rw, no
// sync, SoA conflict-free) -> regs <=128 -> 512 thr/CTA, 16 warps/SM (4/SMSP).
// B fragments stored SoA (uint4 slot (kt*4+j)*32 + lane): conflict-free LDS.128.
//
// SMEM words: [0,192) W1 | [192,448) b1..b4 | [448,12736) B' L2..4
// (per layer: Wh 2048 | Wl 2048, SoA) | [12736,13760) B5' (Wh 512 | Wl 512) |
// [13760,30144) per-lane A-frag slots: 16 warps x 2 vec x 4 kt x 32 lanes x uint4
#define PD_THREADS 512
#define PD_NW 16
#define SM_W1   0
#define SM_BIAS 192
#define SM_B    448
#define SM_B5   12736
#define SM_A4   3440            /* uint4 index of A-frag area (word 13760/4) */
#define SM_WORDS 30144

__device__ __forceinline__ void pd_mma(float* d,
                                       uint32_t a0, uint32_t a1, uint32_t a2, uint32_t a3,
                                       uint32_t b0, uint32_t b1) {
    asm volatile(
        "mma.sync.aligned.m16n8k16.row.col.f32.f16.f16.f32 "
        "{%0,%1,%2,%3},{%4,%5,%6,%7},{%8,%9},{%0,%1,%2,%3};\n"
        : "+f"(d[0]), "+f"(d[1]), "+f"(d[2]), "+f"(d[3])
        : "r"(a0), "r"(a1), "r"(a2), "r"(a3), "r"(b0), "r"(b1));
}

__device__ __forceinline__ void pd_mma8(float* acc,
                                        uint32_t a0, uint32_t a1, uint32_t a2, uint32_t a3,
                                        uint4 B0, uint4 B1, uint4 B2, uint4 B3) {
    pd_mma(acc + 0,  a0, a1, a2, a3, B0.x, B0.y);
    pd_mma(acc + 4,  a0, a1, a2, a3, B0.z, B0.w);
    pd_mma(acc + 8,  a0, a1, a2, a3, B1.x, B1.y);
    pd_mma(acc + 12, a0, a1, a2, a3, B1.z, B1.w);
    pd_mma(acc + 16, a0, a1, a2, a3, B2.x, B2.y);
    pd_mma(acc + 20, a0, a1, a2, a3, B2.z, B2.w);
    pd_mma(acc + 24, a0, a1, a2, a3, B3.x, B3.y);
    pd_mma(acc + 28, a0, a1, a2, a3, B3.z, B3.w);
}

// 64x64 layer GEMM, A fragments in registers.
__device__ __forceinline__ void pd_gemm64(float* acc, const uint4* Bb4,
                                          const uint32_t* Ah) {
    #pragma unroll
    for (int kt = 0; kt < 4; ++kt) {
        uint32_t a0 = Ah[4*kt+0], a1 = Ah[4*kt+1], a2 = Ah[4*kt+2], a3 = Ah[4*kt+3];
        uint4 B0 = Bb4[kt * 128],      B1 = Bb4[kt * 128 + 32];
        uint4 B2 = Bb4[kt * 128 + 64], B3 = Bb4[kt * 128 + 96];
        pd_mma8(acc, a0, a1, a2, a3, B0, B1, B2, B3);              // x * Wh
        B0 = Bb4[512 + kt * 128];      B1 = Bb4[512 + kt * 128 + 32];
        B2 = Bb4[512 + kt * 128 + 64]; B3 = Bb4[512 + kt * 128 + 96];
        pd_mma8(acc, a0, a1, a2, a3, B0, B1, B2, B3);              // x * Wl
    }
}

// 64x64 layer GEMM, A fragments in per-lane SMEM (uint4 slot kt*32).
__device__ __forceinline__ void pd_gemm64_sm(float* acc, const uint4* Bb4,
                                             const uint4* av) {
    #pragma unroll
    for (int kt = 0; kt < 4; ++kt) {
        uint4 A = av[kt * 32];
        uint4 B0 = Bb4[kt * 128],      B1 = Bb4[kt * 128 + 32];
        uint4 B2 = Bb4[kt * 128 + 64], B3 = Bb4[kt * 128 + 96];
        pd_mma8(acc, A.x, A.y, A.z, A.w, B0, B1, B2, B3);
        B0 = Bb4[512 + kt * 128];      B1 = Bb4[512 + kt * 128 + 32];
        B2 = Bb4[512 + kt * 128 + 64]; B3 = Bb4[512 + kt * 128 + 96];
        pd_mma8(acc, A.x, A.y, A.z, A.w, B0, B1, B2, B3);
    }
}

// Layer-5 GEMM (n=16), A in registers.
__device__ __forceinline__ void pd_gemm16(float* a5, const uint4* B5b4,
                                          const uint32_t* Ah) {
    #pragma unroll
    for (int kt = 0; kt < 4; ++kt) {
        uint32_t a0 = Ah[4*kt+0], a1 = Ah[4*kt+1], a2 = Ah[4*kt+2], a3 = Ah[4*kt+3];
        uint4 H  = B5b4[kt * 32];
        uint4 Lo = B5b4[128 + kt * 32];
        pd_mma(a5 + 0, a0, a1, a2, a3, H.x, H.y);
        pd_mma(a5 + 4, a0, a1, a2, a3, H.z, H.w);
        pd_mma(a5 + 0, a0, a1, a2, a3, Lo.x, Lo.y);
        pd_mma(a5 + 4, a0, a1, a2, a3, Lo.z, Lo.w);
    }
}

// Layer-5 GEMM (n=16), A in per-lane SMEM.
__device__ __forceinline__ void pd_gemm16_sm(float* a5, const uint4* B5b4,
                                             const uint4* av) {
    #pragma unroll
    for (int kt = 0; kt < 4; ++kt) {
        uint4 A  = av[kt * 32];
        uint4 H  = B5b4[kt * 32];
        uint4 Lo = B5b4[128 + kt * 32];
        pd_mma(a5 + 0, A.x, A.y, A.z, A.w, H.x, H.y);
        pd_mma(a5 + 4, A.x, A.y, A.z, A.w, H.z, H.w);
        pd_mma(a5 + 0, A.x, A.y, A.z, A.w, Lo.x, Lo.y);
        pd_mma(a5 + 4, A.x, A.y, A.z, A.w, Lo.z, Lo.w);
    }
}

__device__ __forceinline__ void pd_silu_d(float pre, float& h, float& d) {
    float sig = 1.0f / (1.0f + __expf(-pre));
    h = pre * sig;
    d = fmaf(h, 1.0f - sig, sig);
}

// pack (f0 -> low half, f1 -> high half) as fp16x2
__device__ __forceinline__ uint32_t pd_h2(float f0, float f1) {
    uint32_t r;
    asm("cvt.rn.f16x2.f32 %0, %1, %2;" : "=r"(r) : "f"(f1), "f"(f0));
    return r;
}

// fp16 hi/lo split for weight staging (once per CTA)
__device__ __forceinline__ void pd_splitw(float f0, float f1, uint32_t& hi, uint32_t& lo) {
    __half2 hh = __floats2half2_rn(f0, f1);
    float2 bk = __half22float2(hh);
    __half2 ll = __floats2half2_rn(f0 - bk.x, f1 - bk.y);
    hi = *(uint32_t*)&hh;
    lo = *(uint32_t*)&ll;
}

// D-layout acc[32] -> A fragments in registers.
__device__ __forceinline__ void pd_pack(const float* v, uint32_t* ah) {
    #pragma unroll
    for (int kt = 0; kt < 4; ++kt) {
        ah[4*kt+0] = pd_h2(v[8*kt+0], v[8*kt+1]);
        ah[4*kt+1] = pd_h2(v[8*kt+2], v[8*kt+3]);
        ah[4*kt+2] = pd_h2(v[8*kt+4], v[8*kt+5]);
        ah[4*kt+3] = pd_h2(v[8*kt+6], v[8*kt+7]);
    }
}

// D-layout acc[32] -> A fragments in per-lane SMEM.
__device__ __forceinline__ void pd_pack_sm(const float* v, uint4* av) {
    #pragma unroll
    for (int kt = 0; kt < 4; ++kt) {
        av[kt * 32] = make_uint4(pd_h2(v[8*kt+0], v[8*kt+1]),
                                 pd_h2(v[8*kt+2], v[8*kt+3]),
                                 pd_h2(v[8*kt+4], v[8*kt+5]),
                                 pd_h2(v[8*kt+6], v[8*kt+7]));
    }
}

__device__ __forceinline__ void pd_store(float* __restrict__ out, const float* a5,
                                         int pA, int pB, int N, int j, int tg) {
    if (pA < N) {
        float* o = out + 36 * (size_t)pA + 12 * j;
        *(float2*)(o + 2 * tg) = make_float2(a5[0], a5[1]);
        if (tg < 2) *(float2*)(o + 8 + 2 * tg) = make_float2(a5[4], a5[5]);
    }
    if (pB < N) {
        float* o = out + 36 * (size_t)pB + 12 * j;
        *(float2*)(o + 2 * tg) = make_float2(a5[2], a5[3]);
        if (tg < 2) *(float2*)(o + 8 + 2 * tg) = make_float2(a5[6], a5[7]);
    }
}

__global__ void __launch_bounds__(PD_THREADS, 1)
PartialDerivatives_38706245271665_kernel(
    const float* __restrict__ x,
    const float* __restrict__ W1, const float* __restrict__ b1,
    const float* __restrict__ W2, const float* __restrict__ b2,
    const float* __restrict__ W3, const float* __restrict__ b3,
    const float* __restrict__ W4, const float* __restrict__ b4,
    const float* __restrict__ W5,
    float* __restrict__ out, int N)
{
    extern __shared__ uint32_t sm[];
    float* sW1   = (float*)(sm + SM_W1);
    float* sBias = (float*)(sm + SM_BIAS);
    const int tid = threadIdx.x;

    // ---- stage W1 / biases ----
    for (int i = tid; i < 192; i += PD_THREADS) sW1[i] = W1[i];
    for (int i = tid; i < 64; i += PD_THREADS) {
        sBias[i] = b1[i]; sBias[64 + i] = b2[i];
        sBias[128 + i] = b3[i]; sBias[192 + i] = b4[i];
    }
    // ---- stage B' SoA: word r = ((kt*4+j)*32 + lane)*4 + c ----
    for (int i = tid; i < 3 * 2048; i += PD_THREADS) {
        int L = i >> 11, r = i & 2047;
        int c = r & 3, t = r >> 2;
        int lane_ = t & 31, jj = (t >> 5) & 3, kt = t >> 7;
        int tg_ = lane_ & 3, g_ = lane_ >> 2;
        int nt = 2 * jj + (c >> 1), rr = c & 1;
        int k0 = 16 * kt + 2 * tg_ + 8 * rr;
        int n  = 8 * nt + g_;
        const float* W = (L == 0) ? W2 : (L == 1) ? W3 : W4;
        uint32_t hi, lo;
        pd_splitw(W[k0 * 64 + n], W[(k0 + 1) * 64 + n], hi, lo);
        sm[SM_B + L * 4096 + r] = hi;
        sm[SM_B + L * 4096 + 2048 + r] = lo;
    }
    // ---- stage B5' SoA: word i = (kt*32 + lane)*4 + c ----
    for (int i = tid; i < 512; i += PD_THREADS) {
        int c = i & 3, t = i >> 2;
        int lane_ = t & 31, kt = t >> 5;
        int tg_ = lane_ & 3, g_ = lane_ >> 2;
        int nt = c >> 1, rr = c & 1;
        int k0 = 16 * kt + 2 * tg_ + 8 * rr;
        int n  = 8 * nt + g_;
        float v0 = (n < 12) ? W5[k0 * 12 + n] : 0.0f;
        float v1 = (n < 12) ? W5[(k0 + 1) * 12 + n] : 0.0f;
        uint32_t hi, lo;
        pd_splitw(v0, v1, hi, lo);
        sm[SM_B5 + i] = hi;
        sm[SM_B5 + 512 + i] = lo;
    }
    __syncthreads();

    const int wid  = tid >> 5;
    const int lane = tid & 31;
    const int g    = lane >> 2;
    const int tg   = lane & 3;

    const uint4* Bfrag4  = ((const uint4*)(sm + SM_B))  + lane;   // + L*1024 (uint4)
    const uint4* B5frag4 = ((const uint4*)(sm + SM_B5)) + lane;
    // Per-lane A-frag slots for t1 (av2) and t2 (av3): same-thread rw only.
    uint4* av2 = ((uint4*)sm) + SM_A4 + wid * 256 + lane;
    uint4* av3 = av2 + 128;

    const int nTiles = (N + 15) >> 4;

    for (int wt = blockIdx.x * PD_NW + wid; wt < nTiles; wt += gridDim.x * PD_NW) {
        const int p0 = wt << 4;
        const int pA = p0 + g, pB = p0 + g + 8;

        uint32_t Ah[2][16];   // v0 = h, v1 = t0 in registers

        // ================ layer 1 (K=3), direct into fragments ================
        {
            float xA0 = 0.f, xA1 = 0.f, xA2 = 0.f, xB0 = 0.f, xB1 = 0.f, xB2 = 0.f;
            if (pA < N) {
                const float* xp = x + 3 * (size_t)pA;
                xA0 = __ldg(xp); xA1 = __ldg(xp + 1); xA2 = __ldg(xp + 2);
            }
            if (pB < N) {
                const float* xp = x + 3 * (size_t)pB;
                xB0 = __ldg(xp); xB1 = __ldg(xp + 1); xB2 = __ldg(xp + 2);
            }
            #pragma unroll
            for (int kt = 0; kt < 4; ++kt) {
                uint32_t f2[4], f3[4];
                #pragma unroll
                for (int s = 0; s < 2; ++s) {
                    int f0 = 16 * kt + 2 * tg + 8 * s;
                    float2 w0 = *(float2*)&sW1[f0];
                    float2 w1 = *(float2*)&sW1[64 + f0];
                    float2 w2 = *(float2*)&sW1[128 + f0];
                    float2 bb = *(float2*)&sBias[f0];
                    float hA0, dA0, hA1, dA1, hB0, dB0, hB1, dB1;
                    pd_silu_d(fmaf(xA0, w0.x, fmaf(xA1, w1.x, fmaf(xA2, w2.x, bb.x))), hA0, dA0);
                    pd_silu_d(fmaf(xA0, w0.y, fmaf(xA1, w1.y, fmaf(xA2, w2.y, bb.y))), hA1, dA1);
                    pd_silu_d(fmaf(xB0, w0.x, fmaf(xB1, w1.x, fmaf(xB2, w2.x, bb.x))), hB0, dB0);
                    pd_silu_d(fmaf(xB0, w0.y, fmaf(xB1, w1.y, fmaf(xB2, w2.y, bb.y))), hB1, dB1);
                    int fr = kt * 4 + 2 * s;
                    Ah[0][fr]     = pd_h2(hA0, hA1);
                    Ah[0][fr + 1] = pd_h2(hB0, hB1);
                    Ah[1][fr]     = pd_h2(w0.x * dA0, w0.y * dA1);
                    Ah[1][fr + 1] = pd_h2(w0.x * dB0, w0.y * dB1);
                    f2[2*s]   = pd_h2(w1.x * dA0, w1.y * dA1);
                    f2[2*s+1] = pd_h2(w1.x * dB0, w1.y * dB1);
                    f3[2*s]   = pd_h2(w2.x * dA0, w2.y * dA1);
                    f3[2*s+1] = pd_h2(w2.x * dB0, w2.y * dB1);
                }
                av2[kt * 32] = make_uint4(f2[0], f2[1], f2[2], f2[3]);
                av3[kt * 32] = make_uint4(f3[0], f3[1], f3[2], f3[3]);
            }
        }

        // ================ layers 2..4: MMA + register-local epilogue ================
        float dv[32];
        #pragma unroll 1
        for (int L = 0; L < 3; ++L) {
            const uint4* Bb4  = Bfrag4 + L * 1024;
            const float* bias = sBias + 64 + L * 64;
            const bool lastL  = (L == 2);

            // ---- v0 = h ----
            {
                float acc[32];
                #pragma unroll
                for (int q = 0; q < 32; ++q) acc[q] = 0.f;
                pd_gemm64(acc, Bb4, Ah[0]);
                #pragma unroll
                for (int nt = 0; nt < 8; ++nt) {
                    float2 bb = *(float2*)&bias[8 * nt + 2 * tg];
                    float h0, h1, h2, h3;
                    pd_silu_d(acc[4 * nt + 0] + bb.x, h0, dv[4 * nt + 0]);
                    pd_silu_d(acc[4 * nt + 1] + bb.y, h1, dv[4 * nt + 1]);
                    pd_silu_d(acc[4 * nt + 2] + bb.x, h2, dv[4 * nt + 2]);
                    pd_silu_d(acc[4 * nt + 3] + bb.y, h3, dv[4 * nt + 3]);
                    acc[4 * nt + 0] = h0; acc[4 * nt + 1] = h1;
                    acc[4 * nt + 2] = h2; acc[4 * nt + 3] = h3;
                }
                if (!lastL) pd_pack(acc, Ah[0]);   // h unused after L4
            }
            // ---- v1 = t0 (registers) ----
            {
                float acc[32];
                #pragma unroll
                for (int q = 0; q < 32; ++q) acc[q] = 0.f;
                pd_gemm64(acc, Bb4, Ah[1]);
                #pragma unroll
                for (int q = 0; q < 32; ++q) acc[q] *= dv[q];
                pd_pack(acc, Ah[1]);
            }
            // ---- v2 = t1 (per-lane SMEM) ----
            {
                float acc[32];
                #pragma unroll
                for (int q = 0; q < 32; ++q) acc[q] = 0.f;
                pd_gemm64_sm(acc, Bb4, av2);
                #pragma unroll
                for (int q = 0; q < 32; ++q) acc[q] *= dv[q];
                pd_pack_sm(acc, av2);
            }
            // ---- v3 = t2 (per-lane SMEM) ----
            {
                float acc[32];
                #pragma unroll
                for (int q = 0; q < 32; ++q) acc[q] = 0.f;
                pd_gemm64_sm(acc, Bb4, av3);
                #pragma unroll
                for (int q = 0; q < 32; ++q) acc[q] *= dv[q];
                pd_pack_sm(acc, av3);
            }
        }

        // ================ layer 5: tangents @ W5 (n padded to 16) ================
        {
            float a5[8];
            #pragma unroll
            for (int q = 0; q < 8; ++q) a5[q] = 0.f;
            pd_gemm16(a5, B5frag4, Ah[1]);
            pd_store(out, a5, pA, pB, N, 0, tg);

            #pragma unroll
            for (int q = 0; q < 8; ++q) a5[q] = 0.f;
            pd_gemm16_sm(a5, B5frag4, av2);
            pd_store(out, a5, pA, pB, N, 1, tg);

            #pragma unroll
            for (int q = 0; q < 8; ++q) a5[q] = 0.f;
            pd_gemm16_sm(a5, B5frag4, av3);
            pd_store(out, a5, pA, pB, N, 2, tg);
        }
    }
}

extern "C" void kernel_launch(void* const* d_in, const int* in_sizes, int n_in,
                              void* d_out, int out_size)
{
    const float* x  = (const float*)d_in[0];
    const float* W1 = (const float*)d_in[1];
    const float* b1 = (const float*)d_in[2];
    const float* W2 = (const float*)d_in[3];
    const float* b2 = (const float*)d_in[4];
    const float* W3 = (const float*)d_in[5];
    const float* b3 = (const float*)d_in[6];
    const float* W4 = (const float*)d_in[7];
    const float* b4 = (const float*)d_in[8];
    const float* W5 = (const float*)d_in[9];
    // b5 unused: constant offset has zero Jacobian.

    int N = in_sizes[0] / 3;
    int smemBytes = SM_WORDS * (int)sizeof(uint32_t);   // 120576

    cudaFuncSetAttribute(PartialDerivatives_38706245271665_kernel,
                         cudaFuncAttributeMaxDynamicSharedMemorySize, smemBytes);

    // 152 persistent CTAs, 512 threads (16 warps) each -> 1 CTA/SM, 4 warps/SMSP.
    PartialDerivatives_38706245271665_kernel<<<152, PD_THREADS, smemBytes>>>(
        x, W1, b1, W2, b2, W3, b3, W4, b4, W5, (float*)d_out, N);
}

// round 10
// speedup vs baseline: 1.2337x; 1.2337x over previous
#include <cuda_runtime.h>
#include <cuda_fp16.h>
#include <cstdint>

// Jacobian (3x12) of 3->64->64->64->64->12 SiLU MLP at N=1M points.
// mma.sync m16n8k16 fp16, fp32 accum. 2-term split ON WEIGHTS ONLY:
//   W = Wh + Wl (fp16 planes); product = x_f16*Wh + x_f16*Wl (residual ~2^-11).
// One warp owns a 16-point tile and ALL 4 vectors {h,t0,t1,t2}; D-accumulator
// fragments map register-locally onto next layer's A fragments.
// R10: vector-PAIRED GEMMs — each B fragment is loaded once and feeds two
// vectors' MMAs (B LDS halved, MMA ILP doubled). Pair 1 = (h,t0) A in regs;
// pair 2 = (t1,t2) A in per-lane SMEM slots (same-thread rw, no sync,
// SoA conflict-free). 384 thr/CTA, 168 regs, no spills.
//
// SMEM words: [0,192) W1 | [192,448) b1..b4 | [448,12736) B' L2..4
// (per layer: Wh 2048 | Wl 2048, SoA slot (kt*4+j)*32+lane) |
// [12736,13760) B5' (Wh 512 | Wl 512) |
// [13760,26048) per-lane A-frag slots: 12 warps x 2 vec x 4 kt x 32 x uint4
#define PD_THREADS 384
#define PD_NW 12
#define SM_W1   0
#define SM_BIAS 192
#define SM_B    448
#define SM_B5   12736
#define SM_A4   3440            /* uint4 index of A-frag area (word 13760/4) */
#define SM_WORDS 26048

__device__ __forceinline__ void pd_mma(float* d,
                                       uint32_t a0, uint32_t a1, uint32_t a2, uint32_t a3,
                                       uint32_t b0, uint32_t b1) {
    asm volatile(
        "mma.sync.aligned.m16n8k16.row.col.f32.f16.f16.f32 "
        "{%0,%1,%2,%3},{%4,%5,%6,%7},{%8,%9},{%0,%1,%2,%3};\n"
        : "+f"(d[0]), "+f"(d[1]), "+f"(d[2]), "+f"(d[3])
        : "r"(a0), "r"(a1), "r"(a2), "r"(a3), "r"(b0), "r"(b1));
}

__device__ __forceinline__ void pd_mma8(float* acc,
                                        uint32_t a0, uint32_t a1, uint32_t a2, uint32_t a3,
                                        uint4 B0, uint4 B1, uint4 B2, uint4 B3) {
    pd_mma(acc + 0,  a0, a1, a2, a3, B0.x, B0.y);
    pd_mma(acc + 4,  a0, a1, a2, a3, B0.z, B0.w);
    pd_mma(acc + 8,  a0, a1, a2, a3, B1.x, B1.y);
    pd_mma(acc + 12, a0, a1, a2, a3, B1.z, B1.w);
    pd_mma(acc + 16, a0, a1, a2, a3, B2.x, B2.y);
    pd_mma(acc + 20, a0, a1, a2, a3, B2.z, B2.w);
    pd_mma(acc + 24, a0, a1, a2, a3, B3.x, B3.y);
    pd_mma(acc + 28, a0, a1, a2, a3, B3.z, B3.w);
}

// Paired 64x64 layer GEMM: B loaded ONCE per plane per kt, feeds both vectors.
// A operands supplied per-kt via callables below (regs or per-lane SMEM).
__device__ __forceinline__ void pd_gemm64_pair_rr(float* acc0, float* acc1,
                                                  const uint4* Bb4,
                                                  const uint32_t* A0, const uint32_t* A1) {
    #pragma unroll
    for (int kt = 0; kt < 4; ++kt) {
        uint32_t p0 = A0[4*kt+0], p1 = A0[4*kt+1], p2 = A0[4*kt+2], p3 = A0[4*kt+3];
        uint32_t q0 = A1[4*kt+0], q1 = A1[4*kt+1], q2 = A1[4*kt+2], q3 = A1[4*kt+3];
        uint4 B0 = Bb4[kt * 128],      B1 = Bb4[kt * 128 + 32];
        uint4 B2 = Bb4[kt * 128 + 64], B3 = Bb4[kt * 128 + 96];
        pd_mma8(acc0, p0, p1, p2, p3, B0, B1, B2, B3);   // v0 * Wh
        pd_mma8(acc1, q0, q1, q2, q3, B0, B1, B2, B3);   // v1 * Wh
        B0 = Bb4[512 + kt * 128];      B1 = Bb4[512 + kt * 128 + 32];
        B2 = Bb4[512 + kt * 128 + 64]; B3 = Bb4[512 + kt * 128 + 96];
        pd_mma8(acc0, p0, p1, p2, p3, B0, B1, B2, B3);   // v0 * Wl
        pd_mma8(acc1, q0, q1, q2, q3, B0, B1, B2, B3);   // v1 * Wl
    }
}

// Paired GEMM with both A operands in per-lane SMEM (uint4 slot kt*32).
__device__ __forceinline__ void pd_gemm64_pair_ss(float* acc0, float* acc1,
                                                  const uint4* Bb4,
                                                  const uint4* av0, const uint4* av1) {
    #pragma unroll
    for (int kt = 0; kt < 4; ++kt) {
        uint4 P = av0[kt * 32];
        uint4 Q = av1[kt * 32];
        uint4 B0 = Bb4[kt * 128],      B1 = Bb4[kt * 128 + 32];
        uint4 B2 = Bb4[kt * 128 + 64], B3 = Bb4[kt * 128 + 96];
        pd_mma8(acc0, P.x, P.y, P.z, P.w, B0, B1, B2, B3);
        pd_mma8(acc1, Q.x, Q.y, Q.z, Q.w, B0, B1, B2, B3);
        B0 = Bb4[512 + kt * 128];      B1 = Bb4[512 + kt * 128 + 32];
        B2 = Bb4[512 + kt * 128 + 64]; B3 = Bb4[512 + kt * 128 + 96];
        pd_mma8(acc0, P.x, P.y, P.z, P.w, B0, B1, B2, B3);
        pd_mma8(acc1, Q.x, Q.y, Q.z, Q.w, B0, B1, B2, B3);
    }
}

// Layer-5 tri-GEMM (n=16): B loaded once per kt, feeds all 3 tangents.
// t0 A in registers; t1,t2 A in per-lane SMEM.
__device__ __forceinline__ void pd_gemm16_tri(float* a0, float* a1, float* a2,
                                              const uint4* B5b4, const uint32_t* Ah1,
                                              const uint4* av2, const uint4* av3) {
    #pragma unroll
    for (int kt = 0; kt < 4; ++kt) {
        uint32_t r0 = Ah1[4*kt+0], r1 = Ah1[4*kt+1], r2 = Ah1[4*kt+2], r3 = Ah1[4*kt+3];
        uint4 P = av2[kt * 32];
        uint4 Q = av3[kt * 32];
        uint4 H  = B5b4[kt * 32];
        uint4 Lo = B5b4[128 + kt * 32];
        pd_mma(a0 + 0, r0, r1, r2, r3, H.x, H.y);
        pd_mma(a0 + 4, r0, r1, r2, r3, H.z, H.w);
        pd_mma(a1 + 0, P.x, P.y, P.z, P.w, H.x, H.y);
        pd_mma(a1 + 4, P.x, P.y, P.z, P.w, H.z, H.w);
        pd_mma(a2 + 0, Q.x, Q.y, Q.z, Q.w, H.x, H.y);
        pd_mma(a2 + 4, Q.x, Q.y, Q.z, Q.w, H.z, H.w);
        pd_mma(a0 + 0, r0, r1, r2, r3, Lo.x, Lo.y);
        pd_mma(a0 + 4, r0, r1, r2, r3, Lo.z, Lo.w);
        pd_mma(a1 + 0, P.x, P.y, P.z, P.w, Lo.x, Lo.y);
        pd_mma(a1 + 4, P.x, P.y, P.z, P.w, Lo.z, Lo.w);
        pd_mma(a2 + 0, Q.x, Q.y, Q.z, Q.w, Lo.x, Lo.y);
        pd_mma(a2 + 4, Q.x, Q.y, Q.z, Q.w, Lo.z, Lo.w);
    }
}

__device__ __forceinline__ void pd_silu_d(float pre, float& h, float& d) {
    float sig = 1.0f / (1.0f + __expf(-pre));
    h = pre * sig;
    d = fmaf(h, 1.0f - sig, sig);
}

// pack (f0 -> low half, f1 -> high half) as fp16x2
__device__ __forceinline__ uint32_t pd_h2(float f0, float f1) {
    uint32_t r;
    asm("cvt.rn.f16x2.f32 %0, %1, %2;" : "=r"(r) : "f"(f1), "f"(f0));
    return r;
}

// fp16 hi/lo split for weight staging (once per CTA)
__device__ __forceinline__ void pd_splitw(float f0, float f1, uint32_t& hi, uint32_t& lo) {
    __half2 hh = __floats2half2_rn(f0, f1);
    float2 bk = __half22float2(hh);
    __half2 ll = __floats2half2_rn(f0 - bk.x, f1 - bk.y);
    hi = *(uint32_t*)&hh;
    lo = *(uint32_t*)&ll;
}

// D-layout acc[32] -> A fragments in registers.
__device__ __forceinline__ void pd_pack(const float* v, uint32_t* ah) {
    #pragma unroll
    for (int kt = 0; kt < 4; ++kt) {
        ah[4*kt+0] = pd_h2(v[8*kt+0], v[8*kt+1]);
        ah[4*kt+1] = pd_h2(v[8*kt+2], v[8*kt+3]);
        ah[4*kt+2] = pd_h2(v[8*kt+4], v[8*kt+5]);
        ah[4*kt+3] = pd_h2(v[8*kt+6], v[8*kt+7]);
    }
}

// D-layout acc[32] -> A fragments in per-lane SMEM.
__device__ __forceinline__ void pd_pack_sm(const float* v, uint4* av) {
    #pragma unroll
    for (int kt = 0; kt < 4; ++kt) {
        av[kt * 32] = make_uint4(pd_h2(v[8*kt+0], v[8*kt+1]),
                                 pd_h2(v[8*kt+2], v[8*kt+3]),
                                 pd_h2(v[8*kt+4], v[8*kt+5]),
                                 pd_h2(v[8*kt+6], v[8*kt+7]));
    }
}

__device__ __forceinline__ void pd_store(float* __restrict__ out, const float* a5,
                                         int pA, int pB, int N, int j, int tg) {
    if (pA < N) {
        float* o = out + 36 * (size_t)pA + 12 * j;
        *(float2*)(o + 2 * tg) = make_float2(a5[0], a5[1]);
        if (tg < 2) *(float2*)(o + 8 + 2 * tg) = make_float2(a5[4], a5[5]);
    }
    if (pB < N) {
        float* o = out + 36 * (size_t)pB + 12 * j;
        *(float2*)(o + 2 * tg) = make_float2(a5[2], a5[3]);
        if (tg < 2) *(float2*)(o + 8 + 2 * tg) = make_float2(a5[6], a5[7]);
    }
}

__global__ void __launch_bounds__(PD_THREADS)
PartialDerivatives_38706245271665_kernel(
    const float* __restrict__ x,
    const float* __restrict__ W1, const float* __restrict__ b1,
    const float* __restrict__ W2, const float* __restrict__ b2,
    const float* __restrict__ W3, const float* __restrict__ b3,
    const float* __restrict__ W4, const float* __restrict__ b4,
    const float* __restrict__ W5,
    float* __restrict__ out, int N)
{
    extern __shared__ uint32_t sm[];
    float* sW1   = (float*)(sm + SM_W1);
    float* sBias = (float*)(sm + SM_BIAS);
    const int tid = threadIdx.x;

    // ---- stage W1 / biases ----
    for (int i = tid; i < 192; i += PD_THREADS) sW1[i] = W1[i];
    for (int i = tid; i < 64; i += PD_THREADS) {
        sBias[i] = b1[i]; sBias[64 + i] = b2[i];
        sBias[128 + i] = b3[i]; sBias[192 + i] = b4[i];
    }
    // ---- stage B' SoA: word r = ((kt*4+j)*32 + lane)*4 + c ----
    for (int i = tid; i < 3 * 2048; i += PD_THREADS) {
        int L = i >> 11, r = i & 2047;
        int c = r & 3, t = r >> 2;
        int lane_ = t & 31, jj = (t >> 5) & 3, kt = t >> 7;
        int tg_ = lane_ & 3, g_ = lane_ >> 2;
        int nt = 2 * jj + (c >> 1), rr = c & 1;
        int k0 = 16 * kt + 2 * tg_ + 8 * rr;
        int n  = 8 * nt + g_;
        const float* W = (L == 0) ? W2 : (L == 1) ? W3 : W4;
        uint32_t hi, lo;
        pd_splitw(W[k0 * 64 + n], W[(k0 + 1) * 64 + n], hi, lo);
        sm[SM_B + L * 4096 + r] = hi;
        sm[SM_B + L * 4096 + 2048 + r] = lo;
    }
    // ---- stage B5' SoA: word i = (kt*32 + lane)*4 + c ----
    for (int i = tid; i < 512; i += PD_THREADS) {
        int c = i & 3, t = i >> 2;
        int lane_ = t & 31, kt = t >> 5;
        int tg_ = lane_ & 3, g_ = lane_ >> 2;
        int nt = c >> 1, rr = c & 1;
        int k0 = 16 * kt + 2 * tg_ + 8 * rr;
        int n  = 8 * nt + g_;
        float v0 = (n < 12) ? W5[k0 * 12 + n] : 0.0f;
        float v1 = (n < 12) ? W5[(k0 + 1) * 12 + n] : 0.0f;
        uint32_t hi, lo;
        pd_splitw(v0, v1, hi, lo);
        sm[SM_B5 + i] = hi;
        sm[SM_B5 + 512 + i] = lo;
    }
    __syncthreads();

    const int wid  = tid >> 5;
    const int lane = tid & 31;
    const int g    = lane >> 2;
    const int tg   = lane & 3;

    const uint4* Bfrag4  = ((const uint4*)(sm + SM_B))  + lane;   // + L*1024 (uint4)
    const uint4* B5frag4 = ((const uint4*)(sm + SM_B5)) + lane;
    // Per-lane A-frag slots for t1 (av2) and t2 (av3): same-thread rw only.
    uint4* av2 = ((uint4*)sm) + SM_A4 + wid * 256 + lane;
    uint4* av3 = av2 + 128;

    const int nTiles = (N + 15) >> 4;

    for (int wt = blockIdx.x * PD_NW + wid; wt < nTiles; wt += gridDim.x * PD_NW) {
        const int p0 = wt << 4;
        const int pA = p0 + g, pB = p0 + g + 8;

        uint32_t Ah[2][16];   // v0 = h, v1 = t0 in registers

        // ================ layer 1 (K=3), direct into fragments ================
        {
            float xA0 = 0.f, xA1 = 0.f, xA2 = 0.f, xB0 = 0.f, xB1 = 0.f, xB2 = 0.f;
            if (pA < N) {
                const float* xp = x + 3 * (size_t)pA;
                xA0 = __ldg(xp); xA1 = __ldg(xp + 1); xA2 = __ldg(xp + 2);
            }
            if (pB < N) {
                const float* xp = x + 3 * (size_t)pB;
                xB0 = __ldg(xp); xB1 = __ldg(xp + 1); xB2 = __ldg(xp + 2);
            }
            #pragma unroll
            for (int kt = 0; kt < 4; ++kt) {
                uint32_t f2[4], f3[4];
                #pragma unroll
                for (int s = 0; s < 2; ++s) {
                    int f0 = 16 * kt + 2 * tg + 8 * s;
                    float2 w0 = *(float2*)&sW1[f0];
                    float2 w1 = *(float2*)&sW1[64 + f0];
                    float2 w2 = *(float2*)&sW1[128 + f0];
                    float2 bb = *(float2*)&sBias[f0];
                    float hA0, dA0, hA1, dA1, hB0, dB0, hB1, dB1;
                    pd_silu_d(fmaf(xA0, w0.x, fmaf(xA1, w1.x, fmaf(xA2, w2.x, bb.x))), hA0, dA0);
                    pd_silu_d(fmaf(xA0, w0.y, fmaf(xA1, w1.y, fmaf(xA2, w2.y, bb.y))), hA1, dA1);
                    pd_silu_d(fmaf(xB0, w0.x, fmaf(xB1, w1.x, fmaf(xB2, w2.x, bb.x))), hB0, dB0);
                    pd_silu_d(fmaf(xB0, w0.y, fmaf(xB1, w1.y, fmaf(xB2, w2.y, bb.y))), hB1, dB1);
                    int fr = kt * 4 + 2 * s;
                    Ah[0][fr]     = pd_h2(hA0, hA1);
                    Ah[0][fr + 1] = pd_h2(hB0, hB1);
                    Ah[1][fr]     = pd_h2(w0.x * dA0, w0.y * dA1);
                    Ah[1][fr + 1] = pd_h2(w0.x * dB0, w0.y * dB1);
                    f2[2*s]   = pd_h2(w1.x * dA0, w1.y * dA1);
                    f2[2*s+1] = pd_h2(w1.x * dB0, w1.y * dB1);
                    f3[2*s]   = pd_h2(w2.x * dA0, w2.y * dA1);
                    f3[2*s+1] = pd_h2(w2.x * dB0, w2.y * dB1);
                }
                av2[kt * 32] = make_uint4(f2[0], f2[1], f2[2], f2[3]);
                av3[kt * 32] = make_uint4(f3[0], f3[1], f3[2], f3[3]);
            }
        }

        // ================ layers 2..4: paired MMA + register-local epilogue ================
        float dv[32];
        #pragma unroll 1
        for (int L = 0; L < 3; ++L) {
            const uint4* Bb4  = Bfrag4 + L * 1024;
            const float* bias = sBias + 64 + L * 64;
            const bool lastL  = (L == 2);

            // ---- pair 1: (h, t0), A in registers, shared B loads ----
            {
                float acc0[32], acc1[32];
                #pragma unroll
                for (int q = 0; q < 32; ++q) { acc0[q] = 0.f; acc1[q] = 0.f; }
                pd_gemm64_pair_rr(acc0, acc1, Bb4, Ah[0], Ah[1]);
                #pragma unroll
                for (int nt = 0; nt < 8; ++nt) {
                    float2 bb = *(float2*)&bias[8 * nt + 2 * tg];
                    float h0, h1, h2, h3;
                    pd_silu_d(acc0[4 * nt + 0] + bb.x, h0, dv[4 * nt + 0]);
                    pd_silu_d(acc0[4 * nt + 1] + bb.y, h1, dv[4 * nt + 1]);
                    pd_silu_d(acc0[4 * nt + 2] + bb.x, h2, dv[4 * nt + 2]);
                    pd_silu_d(acc0[4 * nt + 3] + bb.y, h3, dv[4 * nt + 3]);
                    acc0[4 * nt + 0] = h0; acc0[4 * nt + 1] = h1;
                    acc0[4 * nt + 2] = h2; acc0[4 * nt + 3] = h3;
                }
                if (!lastL) pd_pack(acc0, Ah[0]);   // h unused after L4
                #pragma unroll
                for (int q = 0; q < 32; ++q) acc1[q] *= dv[q];
                pd_pack(acc1, Ah[1]);
            }
            // ---- pair 2: (t1, t2), A in per-lane SMEM, shared B loads ----
            {
                float acc0[32], acc1[32];
                #pragma unroll
                for (int q = 0; q < 32; ++q) { acc0[q] = 0.f; acc1[q] = 0.f; }
                pd_gemm64_pair_ss(acc0, acc1, Bb4, av2, av3);
                #pragma unroll
                for (int q = 0; q < 32; ++q) { acc0[q] *= dv[q]; acc1[q] *= dv[q]; }
                pd_pack_sm(acc0, av2);
                pd_pack_sm(acc1, av3);
            }
        }

        // ================ layer 5: tri-GEMM, shared B loads ================
        {
            float a50[8], a51[8], a52[8];
            #pragma unroll
            for (int q = 0; q < 8; ++q) { a50[q] = 0.f; a51[q] = 0.f; a52[q] = 0.f; }
            pd_gemm16_tri(a50, a51, a52, B5frag4, Ah[1], av2, av3);
            pd_store(out, a50, pA, pB, N, 0, tg);
            pd_store(out, a51, pA, pB, N, 1, tg);
            pd_store(out, a52, pA, pB, N, 2, tg);
        }
    }
}

extern "C" void kernel_launch(void* const* d_in, const int* in_sizes, int n_in,
                              void* d_out, int out_size)
{
    const float* x  = (const float*)d_in[0];
    const float* W1 = (const float*)d_in[1];
    const float* b1 = (const float*)d_in[2];
    const float* W2 = (const float*)d_in[3];
    const float* b2 = (const float*)d_in[4];
    const float* W3 = (const float*)d_in[5];
    const float* b3 = (const float*)d_in[6];
    const float* W4 = (const float*)d_in[7];
    const float* b4 = (const float*)d_in[8];
    const float* W5 = (const float*)d_in[9];
    // b5 unused: constant offset has zero Jacobian.

    int N = in_sizes[0] / 3;
    int smemBytes = SM_WORDS * (int)sizeof(uint32_t);   // 104192

    cudaFuncSetAttribute(PartialDerivatives_38706245271665_kernel,
                         cudaFuncAttributeMaxDynamicSharedMemorySize, smemBytes);

    // 152 persistent CTAs, 384 threads (12 warps) each -> 1 CTA/SM, 3 warps/SMSP.
    PartialDerivatives_38706245271665_kernel<<<152, PD_THREADS, smemBytes>>>(
        x, W1, b1, W2, b2, W3, b3, W4, b4, W5, (float*)d_out, N);
}

// round 11
// speedup vs baseline: 1.4296x; 1.1588x over previous
#include <cuda_runtime.h>
#include <cuda_fp16.h>
#include <cstdint>

// Jacobian (3x12) of 3->64->64->64->64->12 SiLU MLP at N=1M points.
// mma.sync m16n8k16 fp16, fp32 accum. 2-term split ON WEIGHTS ONLY:
//   W = Wh + Wl (fp16 planes); product = x_f16*Wh + x_f16*Wl (residual ~2^-11).
// One warp owns a 16-point tile + ALL 4 vectors {h,t0,t1,t2}; D-accumulator
// fragments map register-locally onto next layer's A fragments.
// Vector-PAIRED GEMMs: each B fragment loaded once feeds two vectors' MMAs.
// R11: 512 thr/CTA (4 warps/SMSP). To fit 128 regs with zero spills:
//   - t0,t1,t2 A-fragments in per-lane SMEM slots (same-thread rw, no sync)
//   - dv (silu' diagonal) in per-lane SMEM float4 slots, written streaming
//   - epilogues fused per-kt so only 8 dv values are ever live in registers
//
// SMEM words: [0,192) W1 | [192,448) b1..b4 | [448,12736) B' L2..4
// (per layer: Wh 2048 | Wl 2048, SoA slot (kt*4+j)*32+lane) |
// [12736,13760) B5' (Wh 512 | Wl 512) |
// [13760,38336) A-frag slots: 16 warps x 3 vec x 4 kt x 32 lanes x uint4 |
// [38336,54720) dv slots: 16 warps x 8 x 32 lanes x float4
#define PD_THREADS 512
#define PD_NW 16
#define SM_W1   0
#define SM_BIAS 192
#define SM_B    448
#define SM_B5   12736
#define SM_A4   3440            /* uint4 index of A-frag area (word 13760/4) */
#define SM_DV4  9584            /* float4 index of dv area (word 38336/4) */
#define SM_WORDS 54720

__device__ __forceinline__ void pd_mma(float* d,
                                       uint32_t a0, uint32_t a1, uint32_t a2, uint32_t a3,
                                       uint32_t b0, uint32_t b1) {
    asm volatile(
        "mma.sync.aligned.m16n8k16.row.col.f32.f16.f16.f32 "
        "{%0,%1,%2,%3},{%4,%5,%6,%7},{%8,%9},{%0,%1,%2,%3};\n"
        : "+f"(d[0]), "+f"(d[1]), "+f"(d[2]), "+f"(d[3])
        : "r"(a0), "r"(a1), "r"(a2), "r"(a3), "r"(b0), "r"(b1));
}

__device__ __forceinline__ void pd_mma8(float* acc,
                                        uint32_t a0, uint32_t a1, uint32_t a2, uint32_t a3,
                                        uint4 B0, uint4 B1, uint4 B2, uint4 B3) {
    pd_mma(acc + 0,  a0, a1, a2, a3, B0.x, B0.y);
    pd_mma(acc + 4,  a0, a1, a2, a3, B0.z, B0.w);
    pd_mma(acc + 8,  a0, a1, a2, a3, B1.x, B1.y);
    pd_mma(acc + 12, a0, a1, a2, a3, B1.z, B1.w);
    pd_mma(acc + 16, a0, a1, a2, a3, B2.x, B2.y);
    pd_mma(acc + 20, a0, a1, a2, a3, B2.z, B2.w);
    pd_mma(acc + 24, a0, a1, a2, a3, B3.x, B3.y);
    pd_mma(acc + 28, a0, a1, a2, a3, B3.z, B3.w);
}

// Paired 64x64 GEMM: v0 A in registers, v1 A in per-lane SMEM; shared B loads.
__device__ __forceinline__ void pd_gemm64_pair_rs(float* acc0, float* acc1,
                                                  const uint4* Bb4,
                                                  const uint32_t* A0, const uint4* av1) {
    #pragma unroll
    for (int kt = 0; kt < 4; ++kt) {
        uint32_t p0 = A0[4*kt+0], p1 = A0[4*kt+1], p2 = A0[4*kt+2], p3 = A0[4*kt+3];
        uint4 Q = av1[kt * 32];
        uint4 B0 = Bb4[kt * 128],      B1 = Bb4[kt * 128 + 32];
        uint4 B2 = Bb4[kt * 128 + 64], B3 = Bb4[kt * 128 + 96];
        pd_mma8(acc0, p0, p1, p2, p3, B0, B1, B2, B3);   // v0 * Wh
        pd_mma8(acc1, Q.x, Q.y, Q.z, Q.w, B0, B1, B2, B3);
        B0 = Bb4[512 + kt * 128];      B1 = Bb4[512 + kt * 128 + 32];
        B2 = Bb4[512 + kt * 128 + 64]; B3 = Bb4[512 + kt * 128 + 96];
        pd_mma8(acc0, p0, p1, p2, p3, B0, B1, B2, B3);   // v0 * Wl
        pd_mma8(acc1, Q.x, Q.y, Q.z, Q.w, B0, B1, B2, B3);
    }
}

// Paired GEMM with both A operands in per-lane SMEM.
__device__ __forceinline__ void pd_gemm64_pair_ss(float* acc0, float* acc1,
                                                  const uint4* Bb4,
                                                  const uint4* av0, const uint4* av1) {
    #pragma unroll
    for (int kt = 0; kt < 4; ++kt) {
        uint4 P = av0[kt * 32];
        uint4 Q = av1[kt * 32];
        uint4 B0 = Bb4[kt * 128],      B1 = Bb4[kt * 128 + 32];
        uint4 B2 = Bb4[kt * 128 + 64], B3 = Bb4[kt * 128 + 96];
        pd_mma8(acc0, P.x, P.y, P.z, P.w, B0, B1, B2, B3);
        pd_mma8(acc1, Q.x, Q.y, Q.z, Q.w, B0, B1, B2, B3);
        B0 = Bb4[512 + kt * 128];      B1 = Bb4[512 + kt * 128 + 32];
        B2 = Bb4[512 + kt * 128 + 64]; B3 = Bb4[512 + kt * 128 + 96];
        pd_mma8(acc0, P.x, P.y, P.z, P.w, B0, B1, B2, B3);
        pd_mma8(acc1, Q.x, Q.y, Q.z, Q.w, B0, B1, B2, B3);
    }
}

// Layer-5 tri-GEMM (n=16): B loaded once per kt, feeds all 3 tangents (SMEM A).
__device__ __forceinline__ void pd_gemm16_tri(float* a0, float* a1, float* a2,
                                              const uint4* B5b4, const uint4* av1,
                                              const uint4* av2, const uint4* av3) {
    #pragma unroll
    for (int kt = 0; kt < 4; ++kt) {
        uint4 R = av1[kt * 32];
        uint4 P = av2[kt * 32];
        uint4 Q = av3[kt * 32];
        uint4 H  = B5b4[kt * 32];
        uint4 Lo = B5b4[128 + kt * 32];
        pd_mma(a0 + 0, R.x, R.y, R.z, R.w, H.x, H.y);
        pd_mma(a0 + 4, R.x, R.y, R.z, R.w, H.z, H.w);
        pd_mma(a1 + 0, P.x, P.y, P.z, P.w, H.x, H.y);
        pd_mma(a1 + 4, P.x, P.y, P.z, P.w, H.z, H.w);
        pd_mma(a2 + 0, Q.x, Q.y, Q.z, Q.w, H.x, H.y);
        pd_mma(a2 + 4, Q.x, Q.y, Q.z, Q.w, H.z, H.w);
        pd_mma(a0 + 0, R.x, R.y, R.z, R.w, Lo.x, Lo.y);
        pd_mma(a0 + 4, R.x, R.y, R.z, R.w, Lo.z, Lo.w);
        pd_mma(a1 + 0, P.x, P.y, P.z, P.w, Lo.x, Lo.y);
        pd_mma(a1 + 4, P.x, P.y, P.z, P.w, Lo.z, Lo.w);
        pd_mma(a2 + 0, Q.x, Q.y, Q.z, Q.w, Lo.x, Lo.y);
        pd_mma(a2 + 4, Q.x, Q.y, Q.z, Q.w, Lo.z, Lo.w);
    }
}

__device__ __forceinline__ void pd_silu_d(float pre, float& h, float& d) {
    float sig = 1.0f / (1.0f + __expf(-pre));
    h = pre * sig;
    d = fmaf(h, 1.0f - sig, sig);
}

// pack (f0 -> low half, f1 -> high half) as fp16x2
__device__ __forceinline__ uint32_t pd_h2(float f0, float f1) {
    uint32_t r;
    asm("cvt.rn.f16x2.f32 %0, %1, %2;" : "=r"(r) : "f"(f1), "f"(f0));
    return r;
}

// fp16 hi/lo split for weight staging (once per CTA)
__device__ __forceinline__ void pd_splitw(float f0, float f1, uint32_t& hi, uint32_t& lo) {
    __half2 hh = __floats2half2_rn(f0, f1);
    float2 bk = __half22float2(hh);
    __half2 ll = __floats2half2_rn(f0 - bk.x, f1 - bk.y);
    hi = *(uint32_t*)&hh;
    lo = *(uint32_t*)&ll;
}

__device__ __forceinline__ void pd_store(float* __restrict__ out, const float* a5,
                                         int pA, int pB, int N, int j, int tg) {
    if (pA < N) {
        float* o = out + 36 * (size_t)pA + 12 * j;
        *(float2*)(o + 2 * tg) = make_float2(a5[0], a5[1]);
        if (tg < 2) *(float2*)(o + 8 + 2 * tg) = make_float2(a5[4], a5[5]);
    }
    if (pB < N) {
        float* o = out + 36 * (size_t)pB + 12 * j;
        *(float2*)(o + 2 * tg) = make_float2(a5[2], a5[3]);
        if (tg < 2) *(float2*)(o + 8 + 2 * tg) = make_float2(a5[6], a5[7]);
    }
}

__global__ void __launch_bounds__(PD_THREADS, 1)
PartialDerivatives_38706245271665_kernel(
    const float* __restrict__ x,
    const float* __restrict__ W1, const float* __restrict__ b1,
    const float* __restrict__ W2, const float* __restrict__ b2,
    const float* __restrict__ W3, const float* __restrict__ b3,
    const float* __restrict__ W4, const float* __restrict__ b4,
    const float* __restrict__ W5,
    float* __restrict__ out, int N)
{
    extern __shared__ uint32_t sm[];
    float* sW1   = (float*)(sm + SM_W1);
    float* sBias = (float*)(sm + SM_BIAS);
    const int tid = threadIdx.x;

    // ---- stage W1 / biases ----
    for (int i = tid; i < 192; i += PD_THREADS) sW1[i] = W1[i];
    for (int i = tid; i < 64; i += PD_THREADS) {
        sBias[i] = b1[i]; sBias[64 + i] = b2[i];
        sBias[128 + i] = b3[i]; sBias[192 + i] = b4[i];
    }
    // ---- stage B' SoA: word r = ((kt*4+j)*32 + lane)*4 + c ----
    for (int i = tid; i < 3 * 2048; i += PD_THREADS) {
        int L = i >> 11, r = i & 2047;
        int c = r & 3, t = r >> 2;
        int lane_ = t & 31, jj = (t >> 5) & 3, kt = t >> 7;
        int tg_ = lane_ & 3, g_ = lane_ >> 2;
        int nt = 2 * jj + (c >> 1), rr = c & 1;
        int k0 = 16 * kt + 2 * tg_ + 8 * rr;
        int n  = 8 * nt + g_;
        const float* W = (L == 0) ? W2 : (L == 1) ? W3 : W4;
        uint32_t hi, lo;
        pd_splitw(W[k0 * 64 + n], W[(k0 + 1) * 64 + n], hi, lo);
        sm[SM_B + L * 4096 + r] = hi;
        sm[SM_B + L * 4096 + 2048 + r] = lo;
    }
    // ---- stage B5' SoA: word i = (kt*32 + lane)*4 + c ----
    for (int i = tid; i < 512; i += PD_THREADS) {
        int c = i & 3, t = i >> 2;
        int lane_ = t & 31, kt = t >> 5;
        int tg_ = lane_ & 3, g_ = lane_ >> 2;
        int nt = c >> 1, rr = c & 1;
        int k0 = 16 * kt + 2 * tg_ + 8 * rr;
        int n  = 8 * nt + g_;
        float v0 = (n < 12) ? W5[k0 * 12 + n] : 0.0f;
        float v1 = (n < 12) ? W5[(k0 + 1) * 12 + n] : 0.0f;
        uint32_t hi, lo;
        pd_splitw(v0, v1, hi, lo);
        sm[SM_B5 + i] = hi;
        sm[SM_B5 + 512 + i] = lo;
    }
    __syncthreads();

    const int wid  = tid >> 5;
    const int lane = tid & 31;
    const int g    = lane >> 2;
    const int tg   = lane & 3;

    const uint4* Bfrag4  = ((const uint4*)(sm + SM_B))  + lane;   // + L*1024 (uint4)
    const uint4* B5frag4 = ((const uint4*)(sm + SM_B5)) + lane;
    // Per-lane A-frag slots for t0/t1/t2 (same-thread rw only, conflict-free).
    uint4* av1 = ((uint4*)sm) + SM_A4 + wid * 384 + lane;
    uint4* av2 = av1 + 128;
    uint4* av3 = av1 + 256;
    // Per-lane dv slots: sdv[nt*32] holds dv[4nt..4nt+3].
    float4* sdv = ((float4*)sm) + SM_DV4 + wid * 256 + lane;

    const int nTiles = (N + 15) >> 4;

    for (int wt = blockIdx.x * PD_NW + wid; wt < nTiles; wt += gridDim.x * PD_NW) {
        const int p0 = wt << 4;
        const int pA = p0 + g, pB = p0 + g + 8;

        uint32_t Ah0[16];   // h fragments in registers

        // ================ layer 1 (K=3), direct into fragments ================
        {
            float xA0 = 0.f, xA1 = 0.f, xA2 = 0.f, xB0 = 0.f, xB1 = 0.f, xB2 = 0.f;
            if (pA < N) {
                const float* xp = x + 3 * (size_t)pA;
                xA0 = __ldg(xp); xA1 = __ldg(xp + 1); xA2 = __ldg(xp + 2);
            }
            if (pB < N) {
                const float* xp = x + 3 * (size_t)pB;
                xB0 = __ldg(xp); xB1 = __ldg(xp + 1); xB2 = __ldg(xp + 2);
            }
            #pragma unroll
            for (int kt = 0; kt < 4; ++kt) {
                uint32_t f1[4], f2[4], f3[4];
                #pragma unroll
                for (int s = 0; s < 2; ++s) {
                    int f0 = 16 * kt + 2 * tg + 8 * s;
                    float2 w0 = *(float2*)&sW1[f0];
                    float2 w1 = *(float2*)&sW1[64 + f0];
                    float2 w2 = *(float2*)&sW1[128 + f0];
                    float2 bb = *(float2*)&sBias[f0];
                    float hA0, dA0, hA1, dA1, hB0, dB0, hB1, dB1;
                    pd_silu_d(fmaf(xA0, w0.x, fmaf(xA1, w1.x, fmaf(xA2, w2.x, bb.x))), hA0, dA0);
                    pd_silu_d(fmaf(xA0, w0.y, fmaf(xA1, w1.y, fmaf(xA2, w2.y, bb.y))), hA1, dA1);
                    pd_silu_d(fmaf(xB0, w0.x, fmaf(xB1, w1.x, fmaf(xB2, w2.x, bb.x))), hB0, dB0);
                    pd_silu_d(fmaf(xB0, w0.y, fmaf(xB1, w1.y, fmaf(xB2, w2.y, bb.y))), hB1, dB1);
                    int fr = kt * 4 + 2 * s;
                    Ah0[fr]     = pd_h2(hA0, hA1);
                    Ah0[fr + 1] = pd_h2(hB0, hB1);
                    f1[2*s]   = pd_h2(w0.x * dA0, w0.y * dA1);
                    f1[2*s+1] = pd_h2(w0.x * dB0, w0.y * dB1);
                    f2[2*s]   = pd_h2(w1.x * dA0, w1.y * dA1);
                    f2[2*s+1] = pd_h2(w1.x * dB0, w1.y * dB1);
                    f3[2*s]   = pd_h2(w2.x * dA0, w2.y * dA1);
                    f3[2*s+1] = pd_h2(w2.x * dB0, w2.y * dB1);
                }
                av1[kt * 32] = make_uint4(f1[0], f1[1], f1[2], f1[3]);
                av2[kt * 32] = make_uint4(f2[0], f2[1], f2[2], f2[3]);
                av3[kt * 32] = make_uint4(f3[0], f3[1], f3[2], f3[3]);
            }
        }

        // ================ layers 2..4: paired MMA + per-kt fused epilogues ================
        #pragma unroll 1
        for (int L = 0; L < 3; ++L) {
            const uint4* Bb4  = Bfrag4 + L * 1024;
            const float* bias = sBias + 64 + L * 64;
            const bool lastL  = (L == 2);

            // ---- pair 1: (h regs, t0 smem), shared B loads ----
            {
                float acc0[32], acc1[32];
                #pragma unroll
                for (int q = 0; q < 32; ++q) { acc0[q] = 0.f; acc1[q] = 0.f; }
                pd_gemm64_pair_rs(acc0, acc1, Bb4, Ah0, av1);
                // epilogue fused per kt: silu on acc0 -> h,dv; dv to SMEM;
                // scale acc1 by dv; pack both.
                #pragma unroll
                for (int kt = 0; kt < 4; ++kt) {
                    float hv[8];
                    #pragma unroll
                    for (int s = 0; s < 2; ++s) {
                        int nt = 2 * kt + s;
                        float2 bb = *(float2*)&bias[8 * nt + 2 * tg];
                        float d0, d1, d2, d3;
                        pd_silu_d(acc0[4 * nt + 0] + bb.x, hv[4*s+0], d0);
                        pd_silu_d(acc0[4 * nt + 1] + bb.y, hv[4*s+1], d1);
                        pd_silu_d(acc0[4 * nt + 2] + bb.x, hv[4*s+2], d2);
                        pd_silu_d(acc0[4 * nt + 3] + bb.y, hv[4*s+3], d3);
                        sdv[nt * 32] = make_float4(d0, d1, d2, d3);
                        acc1[4 * nt + 0] *= d0; acc1[4 * nt + 1] *= d1;
                        acc1[4 * nt + 2] *= d2; acc1[4 * nt + 3] *= d3;
                    }
                    if (!lastL) {
                        Ah0[4*kt+0] = pd_h2(hv[0], hv[1]);
                        Ah0[4*kt+1] = pd_h2(hv[2], hv[3]);
                        Ah0[4*kt+2] = pd_h2(hv[4], hv[5]);
                        Ah0[4*kt+3] = pd_h2(hv[6], hv[7]);
                    }
                    av1[kt * 32] = make_uint4(pd_h2(acc1[8*kt+0], acc1[8*kt+1]),
                                              pd_h2(acc1[8*kt+2], acc1[8*kt+3]),
                                              pd_h2(acc1[8*kt+4], acc1[8*kt+5]),
                                              pd_h2(acc1[8*kt+6], acc1[8*kt+7]));
                }
            }
            // ---- pair 2: (t1, t2) smem A, shared B loads ----
            {
                float acc0[32], acc1[32];
                #pragma unroll
                for (int q = 0; q < 32; ++q) { acc0[q] = 0.f; acc1[q] = 0.f; }
                pd_gemm64_pair_ss(acc0, acc1, Bb4, av2, av3);
                #pragma unroll
                for (int kt = 0; kt < 4; ++kt) {
                    float4 dA = sdv[(2 * kt) * 32];
                    float4 dB = sdv[(2 * kt + 1) * 32];
                    acc0[8*kt+0] *= dA.x; acc0[8*kt+1] *= dA.y;
                    acc0[8*kt+2] *= dA.z; acc0[8*kt+3] *= dA.w;
                    acc0[8*kt+4] *= dB.x; acc0[8*kt+5] *= dB.y;
                    acc0[8*kt+6] *= dB.z; acc0[8*kt+7] *= dB.w;
                    acc1[8*kt+0] *= dA.x; acc1[8*kt+1] *= dA.y;
                    acc1[8*kt+2] *= dA.z; acc1[8*kt+3] *= dA.w;
                    acc1[8*kt+4] *= dB.x; acc1[8*kt+5] *= dB.y;
                    acc1[8*kt+6] *= dB.z; acc1[8*kt+7] *= dB.w;
                    av2[kt * 32] = make_uint4(pd_h2(acc0[8*kt+0], acc0[8*kt+1]),
                                              pd_h2(acc0[8*kt+2], acc0[8*kt+3]),
                                              pd_h2(acc0[8*kt+4], acc0[8*kt+5]),
                                              pd_h2(acc0[8*kt+6], acc0[8*kt+7]));
                    av3[kt * 32] = make_uint4(pd_h2(acc1[8*kt+0], acc1[8*kt+1]),
                                              pd_h2(acc1[8*kt+2], acc1[8*kt+3]),
                                              pd_h2(acc1[8*kt+4], acc1[8*kt+5]),
                                              pd_h2(acc1[8*kt+6], acc1[8*kt+7]));
                }
            }
        }

        // ================ layer 5: tri-GEMM, shared B loads ================
        {
            float a50[8], a51[8], a52[8];
            #pragma unroll
            for (int q = 0; q < 8; ++q) { a50[q] = 0.f; a51[q] = 0.f; a52[q] = 0.f; }
            pd_gemm16_tri(a50, a51, a52, B5frag4, av1, av2, av3);
            pd_store(out, a50, pA, pB, N, 0, tg);
            pd_store(out, a51, pA, pB, N, 1, tg);
            pd_store(out, a52, pA, pB, N, 2, tg);
        }
    }
}

extern "C" void kernel_launch(void* const* d_in, const int* in_sizes, int n_in,
                              void* d_out, int out_size)
{
    const float* x  = (const float*)d_in[0];
    const float* W1 = (const float*)d_in[1];
    const float* b1 = (const float*)d_in[2];
    const float* W2 = (const float*)d_in[3];
    const float* b2 = (const float*)d_in[4];
    const float* W3 = (const float*)d_in[5];
    const float* b3 = (const float*)d_in[6];
    const float* W4 = (const float*)d_in[7];
    const float* b4 = (const float*)d_in[8];
    const float* W5 = (const float*)d_in[9];
    // b5 unused: constant offset has zero Jacobian.

    int N = in_sizes[0] / 3;
    int smemBytes = SM_WORDS * (int)sizeof(uint32_t);   // 218880

    cudaFuncSetAttribute(PartialDerivatives_38706245271665_kernel,
                         cudaFuncAttributeMaxDynamicSharedMemorySize, smemBytes);

    // 152 persistent CTAs, 512 threads (16 warps) each -> 1 CTA/SM, 4 warps/SMSP.
    PartialDerivatives_38706245271665_kernel<<<152, PD_THREADS, smemBytes>>>(
        x, W1, b1, W2, b2, W3, b3, W4, b4, W5, (float*)d_out, N);
}